// round 12
// baseline (speedup 1.0000x reference)
#include <cuda_runtime.h>
#include <cuda_bf16.h>
#include <math.h>

#define NE 32768
#define NSTEP 65535   // 2*NE - 1

// ---------------- device scratch (static, no allocation) ----------------
__device__ __align__(16) float g_encp[NE * 200];      // projected encodings (h|c)
__device__ __align__(16) float g_PC[NE * 640];        // [0..500)=P row, [512..612)=c_e
__device__ __align__(16) float g_X[NE * 200];         // merge chain states (h|c)
__device__ __align__(16) float g_WtProj[768 * 200];   // W_proj transposed
__device__ __align__(16) float g_WtE[100 * 500];      // W_tree[:,100:200] transposed
__device__ __align__(16) float g_WL[600 * 24];        // concat loss weights
__device__ float g_bL[24];
__device__ float g_losses[NSTEP];

__device__ __forceinline__ float sig_t(float x)  { return 0.5f * __tanhf(0.5f * x) + 0.5f; }

__device__ __forceinline__ void mma16816(float* d, const unsigned* a,
                                         unsigned b0, unsigned b1) {
    asm volatile(
        "mma.sync.aligned.m16n8k16.row.col.f32.bf16.bf16.f32 "
        "{%0,%1,%2,%3}, {%4,%5,%6,%7}, {%8,%9}, {%0,%1,%2,%3};"
        : "+f"(d[0]), "+f"(d[1]), "+f"(d[2]), "+f"(d[3])
        : "r"(a[0]), "r"(a[1]), "r"(a[2]), "r"(a[3]), "r"(b0), "r"(b1));
}

// ---------------- prep: transposes / packing ----------------
__global__ void prep_kernel(const float* __restrict__ Wproj,
                            const float* __restrict__ Wtree,
                            const float* __restrict__ Wact,
                            const float* __restrict__ Wlab,
                            const float* __restrict__ Wdir,
                            const float* __restrict__ bact,
                            const float* __restrict__ blab,
                            const float* __restrict__ bdir) {
    int i = blockIdx.x * blockDim.x + threadIdx.x;
    int stride = gridDim.x * blockDim.x;
    for (int e = i; e < 768 * 200; e += stride) {
        int k = e / 200, j = e % 200;
        g_WtProj[e] = Wproj[j * 768 + k];
    }
    for (int e = i; e < 100 * 500; e += stride) {
        int c = e / 500, r = e % 500;
        g_WtE[e] = Wtree[r * 200 + 100 + c];
    }
    for (int e = i; e < 600 * 24; e += stride) {
        int c = e / 24, q = e % 24;
        float v;
        if (q < 2)       v = Wact[q * 600 + c];
        else if (q < 21) v = Wlab[(q - 2) * 600 + c];
        else             v = Wdir[(q - 21) * 600 + c];
        g_WL[e] = v;
    }
    if (i < 24) {
        g_bL[i] = (i < 2) ? bact[i] : (i < 21) ? blab[i - 2] : bdir[i - 21];
    }
}

// ---------------- generic fp32 GEMM: C[M,N] = A[M,lda] * B[K,N] + bias ----------------
__global__ void gemm_kernel(const float* __restrict__ A, int lda,
                            const float* __restrict__ B,
                            const float* __restrict__ bias,
                            float* __restrict__ C, int ldc,
                            int N, int K) {
    __shared__ float As[16][68];
    __shared__ float Bs[16][64];
    int m0 = blockIdx.y * 64;
    int n0 = blockIdx.x * 64;
    int tid = threadIdx.x;
    int r0 = (tid >> 3) * 4;
    int c0 = (tid & 7) * 8;
    float acc[4][8];
    #pragma unroll
    for (int i = 0; i < 4; i++)
        #pragma unroll
        for (int j = 0; j < 8; j++) acc[i][j] = 0.f;

    for (int k0 = 0; k0 < K; k0 += 16) {
        #pragma unroll
        for (int i = 0; i < 8; i++) {
            int e = tid + 128 * i;
            int m = e >> 4, k = e & 15;
            As[k][m] = (k0 + k < K) ? A[(m0 + m) * lda + k0 + k] : 0.f;
        }
        #pragma unroll
        for (int i = 0; i < 8; i++) {
            int e = tid + 128 * i;
            int k = e >> 6, n = e & 63;
            float v = 0.f;
            if (k0 + k < K && n0 + n < N) v = B[(k0 + k) * N + n0 + n];
            Bs[k][n] = v;
        }
        __syncthreads();
        #pragma unroll
        for (int kk = 0; kk < 16; kk++) {
            float a[4];
            #pragma unroll
            for (int i = 0; i < 4; i++) a[i] = As[kk][r0 + i];
            float4 b0 = *(const float4*)&Bs[kk][c0];
            float4 b1 = *(const float4*)&Bs[kk][c0 + 4];
            float b[8] = {b0.x, b0.y, b0.z, b0.w, b1.x, b1.y, b1.z, b1.w};
            #pragma unroll
            for (int i = 0; i < 4; i++)
                #pragma unroll
                for (int j = 0; j < 8; j++) acc[i][j] += a[i] * b[j];
        }
        __syncthreads();
    }
    #pragma unroll
    for (int i = 0; i < 4; i++) {
        int m = m0 + r0 + i;
        #pragma unroll
        for (int j = 0; j < 8; j++) {
            int n = n0 + c0 + j;
            if (n < N) C[m * ldc + n] = acc[i][j] + bias[n];
        }
    }
}

// ---------------- copy c_e into the packed PC rows ----------------
__global__ void copyc_kernel() {
    int i = blockIdx.x * blockDim.x + threadIdx.x;
    int stride = gridDim.x * blockDim.x;
    for (int e = i; e < NE * 25; e += stride) {
        int m = e / 25, q = e % 25;
        const float4* src = (const float4*)(g_encp + (size_t)m * 200 + 100);
        float4* dst = (float4*)(g_PC + (size_t)m * 640 + 512);
        dst[q] = src[q];
    }
}

// ---------------- TreeLSTM chain: HMMA matvec, split chains + P-preload ----------------
// W_h (500x100) zero-padded to 512x112 bf16 in A-fragments: 16 warps x 2 m-tiles x 7 kt.
// Per iter: accumulators initialized with P[m] (t4==0, col-0 lanes); two chains per
// m-tile (kt 0-3, 4-6) -> dependency depth 4; merge with 1 FADD; STS col-0 to gs.
// Gates (threads 0..99): gi..gu read gs only (P already inside); ce2 from psm.
// Warp 16: cp.async PC row m+3 into 4-slot ring, wait_group 2.
__global__ void __launch_bounds__(544, 1) chain_kernel(const float* __restrict__ Wtree) {
    __shared__ __align__(16) __nv_bfloat16 hs[112];
    __shared__ __align__(16) float gs[512];
    __shared__ __align__(16) float psm[4][640];
    int tid = threadIdx.x;
    int wid = tid >> 5;
    int lane = tid & 31;
    int grp = lane >> 2;   // 0..7
    int t4 = lane & 3;     // 0..3

    // ---- load A fragments (W rows [32*wid, 32*wid+32), bf16, zero-padded) ----
    unsigned afr[2][7][4];
    if (wid < 16) {
        #pragma unroll
        for (int mt = 0; mt < 2; mt++) {
            int R0 = 32 * wid + 16 * mt;
            #pragma unroll
            for (int kt = 0; kt < 7; kt++) {
                #pragma unroll
                for (int j = 0; j < 4; j++) {
                    int row = R0 + grp + ((j & 1) ? 8 : 0);
                    int col = 16 * kt + 2 * t4 + ((j & 2) ? 8 : 0);
                    float lo = 0.f, hi = 0.f;
                    if (row < 500) {
                        if (col < 100)     lo = Wtree[(size_t)row * 200 + col];
                        if (col + 1 < 100) hi = Wtree[(size_t)row * 200 + col + 1];
                    }
                    unsigned ulo = (unsigned)__bfloat16_as_ushort(__float2bfloat16(lo));
                    unsigned uhi = (unsigned)__bfloat16_as_ushort(__float2bfloat16(hi));
                    afr[mt][kt][j] = ulo | (uhi << 16);
                }
            }
        }
    } else {
        #pragma unroll
        for (int mt = 0; mt < 2; mt++)
            #pragma unroll
            for (int kt = 0; kt < 7; kt++)
                #pragma unroll
                for (int j = 0; j < 4; j++) afr[mt][kt][j] = 0u;
    }

    float cprev = 0.f;
    if (tid < 100) {
        float h0 = g_encp[tid];
        cprev = g_encp[100 + tid];
        hs[tid] = __float2bfloat16(h0);
        g_X[tid] = h0;
        g_X[100 + tid] = cprev;
    }
    if (tid >= 100 && tid < 112) hs[tid] = __float2bfloat16(0.f);  // K pad

    // prologue: prefetch PC rows 1..3 into ring slots 1..3 (warp 16), drain to <=2 pending
    if (wid == 16) {
        int p = tid - 512;
        #pragma unroll
        for (int s = 1; s <= 3; s++) {
            const float4* src = (const float4*)(g_PC + (size_t)s * 640);
            unsigned sdst = (unsigned)__cvta_generic_to_shared(&psm[s & 3][0]);
            for (int k = p; k < 160; k += 32) {
                asm volatile("cp.async.cg.shared.global [%0], [%1], 16;\n"
                             :: "r"(sdst + k * 16), "l"(src + k) : "memory");
            }
            asm volatile("cp.async.commit_group;\n" ::: "memory");
        }
        asm volatile("cp.async.wait_group 2;\n" ::: "memory");
    }
    __syncthreads();

    for (int m = 1; m <= NE - 2; m++) {
        if (wid == 16) {
            int p = tid - 512;
            int mp = m + 3;
            if (mp < NE) {
                const float4* src = (const float4*)(g_PC + (size_t)mp * 640);
                unsigned sdst = (unsigned)__cvta_generic_to_shared(&psm[mp & 3][0]);
                for (int k = p; k < 160; k += 32) {
                    asm volatile("cp.async.cg.shared.global [%0], [%1], 16;\n"
                                 :: "r"(sdst + k * 16), "l"(src + k) : "memory");
                }
            }
            asm volatile("cp.async.commit_group;\n" ::: "memory");
            asm volatile("cp.async.wait_group 2;\n" ::: "memory");
        } else {
            // B fragments: h pairs (replicated over N by frag construction)
            const unsigned* hbp = (const unsigned*)hs;
            unsigned bfr[7][2];
            #pragma unroll
            for (int kt = 0; kt < 7; kt++) {
                bfr[kt][0] = hbp[8 * kt + t4];
                bfr[kt][1] = hbp[8 * kt + 4 + t4];
            }
            // accumulators: a-chain (kt 0..3) seeded with P[m]; b-chain (kt 4..6) zero
            const float* P = psm[m & 3];
            int rb = 32 * wid;
            float d0a[4] = {0.f, 0.f, 0.f, 0.f};
            float d1a[4] = {0.f, 0.f, 0.f, 0.f};
            float d0b[4] = {0.f, 0.f, 0.f, 0.f};
            float d1b[4] = {0.f, 0.f, 0.f, 0.f};
            if (t4 == 0) {
                int r0 = rb + grp;
                d0a[0] = (r0 < 500)      ? P[r0]       : 0.f;
                d0a[2] = (r0 + 8 < 500)  ? P[r0 + 8]   : 0.f;
                d1a[0] = (r0 + 16 < 500) ? P[r0 + 16]  : 0.f;
                d1a[2] = (r0 + 24 < 500) ? P[r0 + 24]  : 0.f;
            }
            #pragma unroll
            for (int kt = 0; kt < 4; kt++) {
                mma16816(d0a, afr[0][kt], bfr[kt][0], bfr[kt][1]);
                mma16816(d1a, afr[1][kt], bfr[kt][0], bfr[kt][1]);
            }
            #pragma unroll
            for (int kt = 4; kt < 7; kt++) {
                mma16816(d0b, afr[0][kt], bfr[kt][0], bfr[kt][1]);
                mma16816(d1b, afr[1][kt], bfr[kt][0], bfr[kt][1]);
            }
            if (t4 == 0) {
                gs[rb + grp]      = d0a[0] + d0b[0];
                gs[rb + 8 + grp]  = d0a[2] + d0b[2];
                gs[rb + 16 + grp] = d1a[0] + d1b[0];
                gs[rb + 24 + grp] = d1a[2] + d1b[2];
            }
        }
        __syncthreads();
        if (tid < 100) {
            float gi  = gs[tid];
            float gf1 = gs[100 + tid];
            float gf2 = gs[200 + tid];
            float go  = gs[300 + tid];
            float gu  = gs[400 + tid];
            float ce2 = psm[m & 3][512 + tid];
            float cc = sig_t(gi) * __tanhf(gu) + sig_t(gf1) * cprev + sig_t(gf2) * ce2;
            float hh = sig_t(go) * __tanhf(cc);
            cprev = cc;
            hs[tid] = __float2bfloat16(hh);
            float* Xm = g_X + (size_t)m * 200;
            Xm[tid] = hh;
            Xm[100 + tid] = cc;
        }
        __syncthreads();
    }
}

// ---------------- per-step losses (parallel) ----------------
__device__ __forceinline__ float ce_all(const float* l, int a, int lb, int dr) {
    float m0 = fmaxf(l[0], l[1]);
    float loss = m0 + __logf(__expf(l[0] - m0) + __expf(l[1] - m0)) - l[a];
    float m1 = l[2];
    #pragma unroll
    for (int q = 3; q < 21; q++) m1 = fmaxf(m1, l[q]);
    float s1 = 0.f;
    #pragma unroll
    for (int q = 2; q < 21; q++) s1 += __expf(l[q] - m1);
    loss += m1 + __logf(s1) - l[2 + lb];
    float m2 = fmaxf(fmaxf(l[21], l[22]), l[23]);
    float s2 = __expf(l[21] - m2) + __expf(l[22] - m2) + __expf(l[23] - m2);
    loss += m2 + __logf(s2) - l[21 + dr];
    return loss;
}

__global__ void loss_kernel(const float* __restrict__ missing,
                            const int* __restrict__ ga,
                            const int* __restrict__ gl,
                            const int* __restrict__ gd) {
    __shared__ float fs[16][600];
    int t0 = blockIdx.x * 16;
    int tid = threadIdx.x;

    for (int e = tid; e < 16 * 600; e += 256) {
        int s = e / 600, c = e % 600;
        int t = t0 + s;
        float v = 0.f;
        if (t < NSTEP) {
            const float* src;
            int base;
            if (c < 200) {          // s1
                base = 0;
                if ((t & 1) == 0 && t >= 2) src = g_X + (size_t)(t / 2 - 1) * 200;
                else                         src = missing;
            } else if (c < 400) {   // s0
                base = 200;
                if (t & 1)       src = g_X + (size_t)(t / 2) * 200;
                else             src = (t == 0) ? missing : (g_encp + (size_t)(t / 2) * 200);
            } else {                // b
                base = 400;
                if (t == 0) src = g_encp;
                else {
                    int idx = t / 2 + 1;
                    src = (idx < NE) ? (g_encp + (size_t)idx * 200) : missing;
                }
            }
            v = src[c - base];
        }
        fs[s][c] = v;
    }
    __syncthreads();

    int warp = tid >> 5, lane = tid & 31;
    const float* f0 = fs[warp * 2];
    const float* f1 = fs[warp * 2 + 1];
    float acc0[24], acc1[24];
    #pragma unroll
    for (int q = 0; q < 24; q++) { acc0[q] = 0.f; acc1[q] = 0.f; }

    for (int c = lane; c < 600; c += 32) {
        float fa = f0[c], fb = f1[c];
        const float4* wp = (const float4*)(g_WL + c * 24);
        #pragma unroll
        for (int v4 = 0; v4 < 6; v4++) {
            float4 wv = wp[v4];
            acc0[v4 * 4 + 0] += wv.x * fa;  acc1[v4 * 4 + 0] += wv.x * fb;
            acc0[v4 * 4 + 1] += wv.y * fa;  acc1[v4 * 4 + 1] += wv.y * fb;
            acc0[v4 * 4 + 2] += wv.z * fa;  acc1[v4 * 4 + 2] += wv.z * fb;
            acc0[v4 * 4 + 3] += wv.w * fa;  acc1[v4 * 4 + 3] += wv.w * fb;
        }
    }
    #pragma unroll
    for (int off = 16; off; off >>= 1) {
        #pragma unroll
        for (int q = 0; q < 24; q++) {
            acc0[q] += __shfl_xor_sync(0xffffffffu, acc0[q], off);
            acc1[q] += __shfl_xor_sync(0xffffffffu, acc1[q], off);
        }
    }
    if (lane == 0) {
        int ta = t0 + warp * 2;
        if (ta < NSTEP) {
            float l[24];
            #pragma unroll
            for (int q = 0; q < 24; q++) l[q] = acc0[q] + g_bL[q];
            g_losses[ta] = ce_all(l, ga[ta], gl[ta], gd[ta]);
        }
        int tb = ta + 1;
        if (tb < NSTEP) {
            float l[24];
            #pragma unroll
            for (int q = 0; q < 24; q++) l[q] = acc1[q] + g_bL[q];
            g_losses[tb] = ce_all(l, ga[tb], gl[tb], gd[tb]);
        }
    }
}

// ---------------- deterministic final reduction ----------------
__global__ void reduce_kernel(float* __restrict__ out) {
    __shared__ float ss[1024];
    float s = 0.f;
    for (int i = threadIdx.x; i < NSTEP; i += 1024) s += g_losses[i];
    ss[threadIdx.x] = s;
    __syncthreads();
    for (int o = 512; o; o >>= 1) {
        if (threadIdx.x < o) ss[threadIdx.x] += ss[threadIdx.x + o];
        __syncthreads();
    }
    if (threadIdx.x == 0) out[0] = ss[0];
}

// ---------------- launch ----------------
extern "C" void kernel_launch(void* const* d_in, const int* in_sizes, int n_in,
                              void* d_out, int out_size) {
    const float* enc_cls = (const float*)d_in[0];
    const float* W_proj  = (const float*)d_in[1];
    const float* b_proj  = (const float*)d_in[2];
    const float* missing = (const float*)d_in[3];
    const float* W_act   = (const float*)d_in[4];
    const float* b_act   = (const float*)d_in[5];
    const float* W_lab   = (const float*)d_in[6];
    const float* b_lab   = (const float*)d_in[7];
    const float* W_dir   = (const float*)d_in[8];
    const float* b_dir   = (const float*)d_in[9];
    const float* W_tree  = (const float*)d_in[10];
    const float* b_tree  = (const float*)d_in[11];
    const int*   ga      = (const int*)d_in[12];
    const int*   gl      = (const int*)d_in[13];
    const int*   gd      = (const int*)d_in[14];

    void *p_encp, *p_PC, *p_WtProj, *p_WtE;
    cudaGetSymbolAddress(&p_encp, g_encp);
    cudaGetSymbolAddress(&p_PC, g_PC);
    cudaGetSymbolAddress(&p_WtProj, g_WtProj);
    cudaGetSymbolAddress(&p_WtE, g_WtE);

    prep_kernel<<<128, 256>>>(W_proj, W_tree, W_act, W_lab, W_dir, b_act, b_lab, b_dir);

    // enc_proj = enc_cls @ W_proj^T + b_proj   (M=32768, N=200, K=768)
    gemm_kernel<<<dim3(4, 512), 128>>>(enc_cls, 768, (const float*)p_WtProj,
                                       b_proj, (float*)p_encp, 200, 200, 768);

    // P = enc_proj[:, :100] @ W_e^T + b_tree   (M=32768, N=500, K=100) -> packed rows
    gemm_kernel<<<dim3(8, 512), 128>>>((const float*)p_encp, 200, (const float*)p_WtE,
                                       b_tree, (float*)p_PC, 640, 500, 100);

    copyc_kernel<<<256, 256>>>();

    chain_kernel<<<1, 544>>>(W_tree);

    loss_kernel<<<4096, 256>>>(missing, ga, gl, gd);

    reduce_kernel<<<1, 1024>>>((float*)d_out);
}

// round 13
// speedup vs baseline: 1.2988x; 1.2988x over previous
#include <cuda_runtime.h>
#include <cuda_bf16.h>
#include <math.h>

#define NE 32768
#define NSTEP 65535   // 2*NE - 1

// ---------------- device scratch (static, no allocation) ----------------
__device__ __align__(16) float g_encp[NE * 200];      // projected encodings (h|c)
__device__ __align__(16) float g_PC[NE * 640];        // [0..500)=P row, [512..612)=c_e
__device__ __align__(16) float g_X[NE * 200];         // merge chain states (h|c)
__device__ __align__(16) float g_WtProj[768 * 200];   // W_proj transposed
__device__ __align__(16) float g_WtE[100 * 500];      // W_tree[:,100:200] transposed
__device__ __align__(16) float g_WL[600 * 24];        // concat loss weights
__device__ float g_bL[24];
__device__ float g_losses[NSTEP];

__device__ __forceinline__ float sig_t(float x)  { return 0.5f * __tanhf(0.5f * x) + 0.5f; }

__device__ __forceinline__ void mma16816(float* d, const unsigned* a,
                                         unsigned b0, unsigned b1) {
    asm volatile(
        "mma.sync.aligned.m16n8k16.row.col.f32.bf16.bf16.f32 "
        "{%0,%1,%2,%3}, {%4,%5,%6,%7}, {%8,%9}, {%0,%1,%2,%3};"
        : "+f"(d[0]), "+f"(d[1]), "+f"(d[2]), "+f"(d[3])
        : "r"(a[0]), "r"(a[1]), "r"(a[2]), "r"(a[3]), "r"(b0), "r"(b1));
}

// ---------------- prep: transposes / packing ----------------
__global__ void prep_kernel(const float* __restrict__ Wproj,
                            const float* __restrict__ Wtree,
                            const float* __restrict__ Wact,
                            const float* __restrict__ Wlab,
                            const float* __restrict__ Wdir,
                            const float* __restrict__ bact,
                            const float* __restrict__ blab,
                            const float* __restrict__ bdir) {
    int i = blockIdx.x * blockDim.x + threadIdx.x;
    int stride = gridDim.x * blockDim.x;
    for (int e = i; e < 768 * 200; e += stride) {
        int k = e / 200, j = e % 200;
        g_WtProj[e] = Wproj[j * 768 + k];
    }
    for (int e = i; e < 100 * 500; e += stride) {
        int c = e / 500, r = e % 500;
        g_WtE[e] = Wtree[r * 200 + 100 + c];
    }
    for (int e = i; e < 600 * 24; e += stride) {
        int c = e / 24, q = e % 24;
        float v;
        if (q < 2)       v = Wact[q * 600 + c];
        else if (q < 21) v = Wlab[(q - 2) * 600 + c];
        else             v = Wdir[(q - 21) * 600 + c];
        g_WL[e] = v;
    }
    if (i < 24) {
        g_bL[i] = (i < 2) ? bact[i] : (i < 21) ? blab[i - 2] : bdir[i - 21];
    }
}

// ---------------- generic fp32 GEMM: C[M,N] = A[M,lda] * B[K,N] + bias ----------------
__global__ void gemm_kernel(const float* __restrict__ A, int lda,
                            const float* __restrict__ B,
                            const float* __restrict__ bias,
                            float* __restrict__ C, int ldc,
                            int N, int K) {
    __shared__ float As[16][68];
    __shared__ float Bs[16][64];
    int m0 = blockIdx.y * 64;
    int n0 = blockIdx.x * 64;
    int tid = threadIdx.x;
    int r0 = (tid >> 3) * 4;
    int c0 = (tid & 7) * 8;
    float acc[4][8];
    #pragma unroll
    for (int i = 0; i < 4; i++)
        #pragma unroll
        for (int j = 0; j < 8; j++) acc[i][j] = 0.f;

    for (int k0 = 0; k0 < K; k0 += 16) {
        #pragma unroll
        for (int i = 0; i < 8; i++) {
            int e = tid + 128 * i;
            int m = e >> 4, k = e & 15;
            As[k][m] = (k0 + k < K) ? A[(m0 + m) * lda + k0 + k] : 0.f;
        }
        #pragma unroll
        for (int i = 0; i < 8; i++) {
            int e = tid + 128 * i;
            int k = e >> 6, n = e & 63;
            float v = 0.f;
            if (k0 + k < K && n0 + n < N) v = B[(k0 + k) * N + n0 + n];
            Bs[k][n] = v;
        }
        __syncthreads();
        #pragma unroll
        for (int kk = 0; kk < 16; kk++) {
            float a[4];
            #pragma unroll
            for (int i = 0; i < 4; i++) a[i] = As[kk][r0 + i];
            float4 b0 = *(const float4*)&Bs[kk][c0];
            float4 b1 = *(const float4*)&Bs[kk][c0 + 4];
            float b[8] = {b0.x, b0.y, b0.z, b0.w, b1.x, b1.y, b1.z, b1.w};
            #pragma unroll
            for (int i = 0; i < 4; i++)
                #pragma unroll
                for (int j = 0; j < 8; j++) acc[i][j] += a[i] * b[j];
        }
        __syncthreads();
    }
    #pragma unroll
    for (int i = 0; i < 4; i++) {
        int m = m0 + r0 + i;
        #pragma unroll
        for (int j = 0; j < 8; j++) {
            int n = n0 + c0 + j;
            if (n < N) C[m * ldc + n] = acc[i][j] + bias[n];
        }
    }
}

// ---------------- copy c_e into the packed PC rows ----------------
__global__ void copyc_kernel() {
    int i = blockIdx.x * blockDim.x + threadIdx.x;
    int stride = gridDim.x * blockDim.x;
    for (int e = i; e < NE * 25; e += stride) {
        int m = e / 25, q = e % 25;
        const float4* src = (const float4*)(g_encp + (size_t)m * 200 + 100);
        float4* dst = (float4*)(g_PC + (size_t)m * 640 + 512);
        dst[q] = src[q];
    }
}

// ---------------- TreeLSTM chain: HMMA (mma.sync bf16) matvec per step ----------------
// (R11 configuration — measured best: 15.30ms, rel_err 7.6e-8.)
// W_h (500x100) zero-padded to 512x112 bf16, held in A-fragments in registers:
//   16 mma warps, warp w owns rows [32w, 32w+32) as 2 m-tiles x 7 k-tiles, 4 regs each.
// Per iteration: B frags from SMEM bf16 h[112] (replicated across N=8 by construction),
//   14 chained mma into f32 D; lanes (lane&3)==0 hold column 0 -> 4 STS to gs.
// Threads 0..99 then apply gates; write new h as bf16 to hs + f32 (h|c) to g_X.
// Warp 16 (threads 512..543): cp.async prefetch of PC row m+2 into 3-slot ring.
__global__ void __launch_bounds__(544, 1) chain_kernel(const float* __restrict__ Wtree) {
    __shared__ __align__(16) __nv_bfloat16 hs[112];
    __shared__ __align__(16) float gs[512];
    __shared__ __align__(16) float psm[3][640];
    int tid = threadIdx.x;
    int wid = tid >> 5;
    int lane = tid & 31;
    int grp = lane >> 2;   // 0..7
    int t4 = lane & 3;     // 0..3

    // ---- load A fragments (W rows [32*wid, 32*wid+32), bf16, zero-padded) ----
    unsigned afr[2][7][4];
    if (wid < 16) {
        #pragma unroll
        for (int mt = 0; mt < 2; mt++) {
            int R0 = 32 * wid + 16 * mt;
            #pragma unroll
            for (int kt = 0; kt < 7; kt++) {
                #pragma unroll
                for (int j = 0; j < 4; j++) {
                    int row = R0 + grp + ((j & 1) ? 8 : 0);
                    int col = 16 * kt + 2 * t4 + ((j & 2) ? 8 : 0);
                    float lo = 0.f, hi = 0.f;
                    if (row < 500) {
                        if (col < 100)     lo = Wtree[(size_t)row * 200 + col];
                        if (col + 1 < 100) hi = Wtree[(size_t)row * 200 + col + 1];
                    }
                    unsigned ulo = (unsigned)__bfloat16_as_ushort(__float2bfloat16(lo));
                    unsigned uhi = (unsigned)__bfloat16_as_ushort(__float2bfloat16(hi));
                    afr[mt][kt][j] = ulo | (uhi << 16);
                }
            }
        }
    } else {
        #pragma unroll
        for (int mt = 0; mt < 2; mt++)
            #pragma unroll
            for (int kt = 0; kt < 7; kt++)
                #pragma unroll
                for (int j = 0; j < 4; j++) afr[mt][kt][j] = 0u;
    }

    float cprev = 0.f;
    if (tid < 100) {
        float h0 = g_encp[tid];
        cprev = g_encp[100 + tid];
        hs[tid] = __float2bfloat16(h0);
        g_X[tid] = h0;
        g_X[100 + tid] = cprev;
    }
    if (tid >= 100 && tid < 112) hs[tid] = __float2bfloat16(0.f);  // K pad, never rewritten

    // prologue: prefetch PC rows 1 and 2 (warp 16)
    if (wid == 16) {
        int p = tid - 512;
        #pragma unroll
        for (int s = 1; s <= 2; s++) {
            const float4* src = (const float4*)(g_PC + (size_t)s * 640);
            unsigned sdst = (unsigned)__cvta_generic_to_shared(&psm[s % 3][0]);
            for (int k = p; k < 160; k += 32) {
                asm volatile("cp.async.cg.shared.global [%0], [%1], 16;\n"
                             :: "r"(sdst + k * 16), "l"(src + k) : "memory");
            }
            asm volatile("cp.async.commit_group;\n" ::: "memory");
        }
    }
    __syncthreads();

    for (int m = 1; m <= NE - 2; m++) {
        if (wid == 16) {
            int p = tid - 512;
            int mp = m + 2;
            if (mp < NE) {
                const float4* src = (const float4*)(g_PC + (size_t)mp * 640);
                unsigned sdst = (unsigned)__cvta_generic_to_shared(&psm[mp % 3][0]);
                for (int k = p; k < 160; k += 32) {
                    asm volatile("cp.async.cg.shared.global [%0], [%1], 16;\n"
                                 :: "r"(sdst + k * 16), "l"(src + k) : "memory");
                }
            }
            asm volatile("cp.async.commit_group;\n" ::: "memory");
            asm volatile("cp.async.wait_group 2;\n" ::: "memory");
        } else {
            // B fragments: h pairs (replicated over N by frag construction)
            const unsigned* hbp = (const unsigned*)hs;
            unsigned bfr[7][2];
            #pragma unroll
            for (int kt = 0; kt < 7; kt++) {
                bfr[kt][0] = hbp[8 * kt + t4];       // {h[16kt+2t], h[16kt+2t+1]}
                bfr[kt][1] = hbp[8 * kt + 4 + t4];   // {h[16kt+8+2t], h[16kt+9+2t]}
            }
            float d0[4] = {0.f, 0.f, 0.f, 0.f};
            float d1[4] = {0.f, 0.f, 0.f, 0.f};
            #pragma unroll
            for (int kt = 0; kt < 7; kt++) {
                mma16816(d0, afr[0][kt], bfr[kt][0], bfr[kt][1]);
                mma16816(d1, afr[1][kt], bfr[kt][0], bfr[kt][1]);
            }
            if (t4 == 0) {
                int rb = 32 * wid;
                gs[rb + grp]      = d0[0];   // row rb+grp      (col 0)
                gs[rb + 8 + grp]  = d0[2];   // row rb+8+grp
                gs[rb + 16 + grp] = d1[0];
                gs[rb + 24 + grp] = d1[2];
            }
        }
        __syncthreads();
        if (tid < 100) {
            const float* P = psm[m % 3];
            float gi  = gs[tid]       + P[tid];
            float gf1 = gs[100 + tid] + P[100 + tid];
            float gf2 = gs[200 + tid] + P[200 + tid];
            float go  = gs[300 + tid] + P[300 + tid];
            float gu  = gs[400 + tid] + P[400 + tid];
            float ce2 = P[512 + tid];
            float cc = sig_t(gi) * __tanhf(gu) + sig_t(gf1) * cprev + sig_t(gf2) * ce2;
            float hh = sig_t(go) * __tanhf(cc);
            cprev = cc;
            hs[tid] = __float2bfloat16(hh);
            float* Xm = g_X + (size_t)m * 200;
            Xm[tid] = hh;
            Xm[100 + tid] = cc;
        }
        __syncthreads();
    }
}

// ---------------- per-step losses (parallel) ----------------
__device__ __forceinline__ float ce_all(const float* l, int a, int lb, int dr) {
    float m0 = fmaxf(l[0], l[1]);
    float loss = m0 + __logf(__expf(l[0] - m0) + __expf(l[1] - m0)) - l[a];
    float m1 = l[2];
    #pragma unroll
    for (int q = 3; q < 21; q++) m1 = fmaxf(m1, l[q]);
    float s1 = 0.f;
    #pragma unroll
    for (int q = 2; q < 21; q++) s1 += __expf(l[q] - m1);
    loss += m1 + __logf(s1) - l[2 + lb];
    float m2 = fmaxf(fmaxf(l[21], l[22]), l[23]);
    float s2 = __expf(l[21] - m2) + __expf(l[22] - m2) + __expf(l[23] - m2);
    loss += m2 + __logf(s2) - l[21 + dr];
    return loss;
}

__global__ void loss_kernel(const float* __restrict__ missing,
                            const int* __restrict__ ga,
                            const int* __restrict__ gl,
                            const int* __restrict__ gd) {
    __shared__ float fs[16][600];
    int t0 = blockIdx.x * 16;
    int tid = threadIdx.x;

    for (int e = tid; e < 16 * 600; e += 256) {
        int s = e / 600, c = e % 600;
        int t = t0 + s;
        float v = 0.f;
        if (t < NSTEP) {
            const float* src;
            int base;
            if (c < 200) {          // s1
                base = 0;
                if ((t & 1) == 0 && t >= 2) src = g_X + (size_t)(t / 2 - 1) * 200;
                else                         src = missing;
            } else if (c < 400) {   // s0
                base = 200;
                if (t & 1)       src = g_X + (size_t)(t / 2) * 200;
                else             src = (t == 0) ? missing : (g_encp + (size_t)(t / 2) * 200);
            } else {                // b
                base = 400;
                if (t == 0) src = g_encp;
                else {
                    int idx = t / 2 + 1;
                    src = (idx < NE) ? (g_encp + (size_t)idx * 200) : missing;
                }
            }
            v = src[c - base];
        }
        fs[s][c] = v;
    }
    __syncthreads();

    int warp = tid >> 5, lane = tid & 31;
    const float* f0 = fs[warp * 2];
    const float* f1 = fs[warp * 2 + 1];
    float acc0[24], acc1[24];
    #pragma unroll
    for (int q = 0; q < 24; q++) { acc0[q] = 0.f; acc1[q] = 0.f; }

    for (int c = lane; c < 600; c += 32) {
        float fa = f0[c], fb = f1[c];
        const float4* wp = (const float4*)(g_WL + c * 24);
        #pragma unroll
        for (int v4 = 0; v4 < 6; v4++) {
            float4 wv = wp[v4];
            acc0[v4 * 4 + 0] += wv.x * fa;  acc1[v4 * 4 + 0] += wv.x * fb;
            acc0[v4 * 4 + 1] += wv.y * fa;  acc1[v4 * 4 + 1] += wv.y * fb;
            acc0[v4 * 4 + 2] += wv.z * fa;  acc1[v4 * 4 + 2] += wv.z * fb;
            acc0[v4 * 4 + 3] += wv.w * fa;  acc1[v4 * 4 + 3] += wv.w * fb;
        }
    }
    #pragma unroll
    for (int off = 16; off; off >>= 1) {
        #pragma unroll
        for (int q = 0; q < 24; q++) {
            acc0[q] += __shfl_xor_sync(0xffffffffu, acc0[q], off);
            acc1[q] += __shfl_xor_sync(0xffffffffu, acc1[q], off);
        }
    }
    if (lane == 0) {
        int ta = t0 + warp * 2;
        if (ta < NSTEP) {
            float l[24];
            #pragma unroll
            for (int q = 0; q < 24; q++) l[q] = acc0[q] + g_bL[q];
            g_losses[ta] = ce_all(l, ga[ta], gl[ta], gd[ta]);
        }
        int tb = ta + 1;
        if (tb < NSTEP) {
            float l[24];
            #pragma unroll
            for (int q = 0; q < 24; q++) l[q] = acc1[q] + g_bL[q];
            g_losses[tb] = ce_all(l, ga[tb], gl[tb], gd[tb]);
        }
    }
}

// ---------------- deterministic final reduction ----------------
__global__ void reduce_kernel(float* __restrict__ out) {
    __shared__ float ss[1024];
    float s = 0.f;
    for (int i = threadIdx.x; i < NSTEP; i += 1024) s += g_losses[i];
    ss[threadIdx.x] = s;
    __syncthreads();
    for (int o = 512; o; o >>= 1) {
        if (threadIdx.x < o) ss[threadIdx.x] += ss[threadIdx.x + o];
        __syncthreads();
    }
    if (threadIdx.x == 0) out[0] = ss[0];
}

// ---------------- launch ----------------
extern "C" void kernel_launch(void* const* d_in, const int* in_sizes, int n_in,
                              void* d_out, int out_size) {
    const float* enc_cls = (const float*)d_in[0];
    const float* W_proj  = (const float*)d_in[1];
    const float* b_proj  = (const float*)d_in[2];
    const float* missing = (const float*)d_in[3];
    const float* W_act   = (const float*)d_in[4];
    const float* b_act   = (const float*)d_in[5];
    const float* W_lab   = (const float*)d_in[6];
    const float* b_lab   = (const float*)d_in[7];
    const float* W_dir   = (const float*)d_in[8];
    const float* b_dir   = (const float*)d_in[9];
    const float* W_tree  = (const float*)d_in[10];
    const float* b_tree  = (const float*)d_in[11];
    const int*   ga      = (const int*)d_in[12];
    const int*   gl      = (const int*)d_in[13];
    const int*   gd      = (const int*)d_in[14];

    void *p_encp, *p_PC, *p_WtProj, *p_WtE;
    cudaGetSymbolAddress(&p_encp, g_encp);
    cudaGetSymbolAddress(&p_PC, g_PC);
    cudaGetSymbolAddress(&p_WtProj, g_WtProj);
    cudaGetSymbolAddress(&p_WtE, g_WtE);

    prep_kernel<<<128, 256>>>(W_proj, W_tree, W_act, W_lab, W_dir, b_act, b_lab, b_dir);

    // enc_proj = enc_cls @ W_proj^T + b_proj   (M=32768, N=200, K=768)
    gemm_kernel<<<dim3(4, 512), 128>>>(enc_cls, 768, (const float*)p_WtProj,
                                       b_proj, (float*)p_encp, 200, 200, 768);

    // P = enc_proj[:, :100] @ W_e^T + b_tree   (M=32768, N=500, K=100) -> packed rows
    gemm_kernel<<<dim3(8, 512), 128>>>((const float*)p_encp, 200, (const float*)p_WtE,
                                       b_tree, (float*)p_PC, 640, 500, 100);

    copyc_kernel<<<256, 256>>>();

    chain_kernel<<<1, 544>>>(W_tree);

    loss_kernel<<<4096, 256>>>(missing, ga, gl, gd);

    reduce_kernel<<<1, 1024>>>((float*)d_out);
}